// round 13
// baseline (speedup 1.0000x reference)
#include <cuda_runtime.h>
#include <cuda_fp16.h>
#include <cstdint>

// ---------------- problem constants ----------------
#define B_    8
#define K_    128
#define S_    256
#define NOUT  16384
#define BK    32                      // k per chunk
#define NST   4
#define STRIP 2048                    // 32k x 64B per warp-strip
#define RINGW (NST * STRIP)           // 8KB per warp
#define A_OFF 65536                   // A resident fp16 [128][256B]
#define SM_TOTAL (A_OFF + 32768)      // 96KB

__device__ __align__(16) __half g_B[K_ * NOUT];      // [k][j]  4MB

__device__ unsigned g_bar_count = 0;
__device__ unsigned g_bar_phase = 0;

// ---------------- helpers ----------------
__device__ __forceinline__ uint32_t smem_u32(const void* p) {
    uint32_t a;
    asm("{ .reg .u64 t; cvta.to.shared.u64 t, %1; cvt.u32.u64 %0, t; }" : "=r"(a) : "l"(p));
    return a;
}
__device__ __forceinline__ void cp_async16(uint32_t saddr, const void* gaddr) {
    asm volatile("cp.async.cg.shared.global [%0], [%1], 16;" :: "r"(saddr), "l"(gaddr));
}
__device__ __forceinline__ void cp_commit() {
    asm volatile("cp.async.commit_group;" ::: "memory");
}
template <int N>
__device__ __forceinline__ void cp_wait() {
    asm volatile("cp.async.wait_group %0;" :: "n"(N) : "memory");
}
__device__ __forceinline__ void ldsm4t(uint32_t& r0, uint32_t& r1, uint32_t& r2, uint32_t& r3,
                                       uint32_t addr) {
    asm volatile("ldmatrix.sync.aligned.m8n8.x4.trans.shared.b16 {%0,%1,%2,%3}, [%4];"
                 : "=r"(r0), "=r"(r1), "=r"(r2), "=r"(r3) : "r"(addr));
}
__device__ __forceinline__ void mma16816(float* d, uint32_t a0, uint32_t a1, uint32_t a2,
                                         uint32_t a3, uint32_t b0, uint32_t b1) {
    asm volatile(
        "mma.sync.aligned.m16n8k16.row.col.f32.f16.f16.f32 "
        "{%0,%1,%2,%3}, {%4,%5,%6,%7}, {%8,%9}, {%0,%1,%2,%3};"
        : "+f"(d[0]), "+f"(d[1]), "+f"(d[2]), "+f"(d[3])
        : "r"(a0), "r"(a1), "r"(a2), "r"(a3), "r"(b0), "r"(b1));
}

#define TSWZ(k, c) ((c) ^ ((k) & 7))

// ---------------- fused persistent kernel ----------------
__global__ __launch_bounds__(256, 2)
void fused_kernel(const float* __restrict__ y, const float* __restrict__ W,
                  float* __restrict__ out) {
    extern __shared__ char smem[];
    const uint32_t sbase = smem_u32(smem);
    const int tid  = threadIdx.x;
    const int bid  = blockIdx.x;
    const int grid = gridDim.x;
    const int lane = tid & 31;
    const int w    = tid >> 5;
    const int wm   = w >> 2;
    const int wn   = w & 3;

    // row-affine work assignment
    const int row   = bid & 15;
    const int slot  = bid >> 4;
    const int slots = grid >> 4;
    const int nn    = row >> 1;
    const int mcol  = (row & 1) * 128;
    const int bx0   = (slot * 128) / slots;
    const int bx1   = ((slot + 1) * 128) / slots;

    // ===== A staging (fp32) into [0,64KB), async =====
    {
        const float* ya = y + (size_t)nn * 32768 + mcol;
        #pragma unroll
        for (int it = 0; it < 16; ++it) {
            int cid = tid + it * 256;
            int k = cid >> 5, cc = cid & 31;
            cp_async16(sbase + k * 512 + ((cc ^ (k & 7)) << 4),
                       ya + (size_t)k * 256 + cc * 4);
        }
        cp_commit();
    }

    // ===== W cast fp32 -> fp16 (grid-strided) =====
    {
        const int nthr = grid << 8;
        for (int u = (bid << 8) + tid; u < 262144; u += nthr) {
            float4 v0 = ((const float4*)(W + (size_t)u * 8))[0];
            float4 v1 = ((const float4*)(W + (size_t)u * 8))[1];
            __half2 h0 = __floats2half2_rn(v0.x, v0.y);
            __half2 h1 = __floats2half2_rn(v0.z, v0.w);
            __half2 h2 = __floats2half2_rn(v1.x, v1.y);
            __half2 h3 = __floats2half2_rn(v1.z, v1.w);
            uint4 o;
            o.x = *(uint32_t*)&h0; o.y = *(uint32_t*)&h1;
            o.z = *(uint32_t*)&h2; o.w = *(uint32_t*)&h3;
            *(uint4*)(g_B + (size_t)u * 8) = o;
        }
    }

    // ===== convert A to resident fp16 [128k][256B] at A_OFF =====
    cp_wait<0>();
    __syncthreads();
    {
        const int k = tid >> 1, half = tid & 1;
        #pragma unroll
        for (int j = 0; j < 8; ++j) {
            int c0 = half * 16 + 2 * j;
            float4 v0 = *(float4*)(smem + k * 512 + ((c0 ^ (k & 7)) << 4));
            float4 v1 = *(float4*)(smem + k * 512 + (((c0 + 1) ^ (k & 7)) << 4));
            __half2 h0 = __floats2half2_rn(v0.x, v0.y);
            __half2 h1 = __floats2half2_rn(v0.z, v0.w);
            __half2 h2 = __floats2half2_rn(v1.x, v1.y);
            __half2 h3 = __floats2half2_rn(v1.z, v1.w);
            uint4 o;
            o.x = *(uint32_t*)&h0; o.y = *(uint32_t*)&h1;
            o.z = *(uint32_t*)&h2; o.w = *(uint32_t*)&h3;
            *(uint4*)(smem + A_OFF + k * 256 + (TSWZ(k, half * 8 + j) << 4)) = o;
        }
    }
    __syncthreads();

    // ===== global barrier (W visibility) =====
    if (tid == 0) {
        unsigned ph = *(volatile unsigned*)&g_bar_phase;
        __threadfence();
        unsigned t = atomicAdd(&g_bar_count, 1u);
        if (t == (unsigned)grid - 1u) {
            g_bar_count = 0;
            __threadfence();
            *(volatile unsigned*)&g_bar_phase = ph ^ 1u;
        } else {
            while (*(volatile unsigned*)&g_bar_phase == ph) __nanosleep(128);
        }
        __threadfence();
    }
    __syncthreads();   // last CTA-wide sync; mainloop is barrier-free

    // ===== per-warp constants =====
    const uint32_t ringBase = sbase + w * RINGW;
    // cp.async: 128 16B chunks per strip, 4 per lane
    uint32_t sOffB[4], gOffB[4];
    #pragma unroll
    for (int i = 0; i < 4; ++i) {
        int id = lane + 32 * i;
        int k = id >> 2, c = id & 3;
        sOffB[i] = (uint32_t)(k * 64 + ((c ^ ((k >> 1) & 3)) << 4));
        gOffB[i] = (uint32_t)(k * NOUT + c * 8);
    }
    // ldsm B (strip layout): ng=0,1 ; +k16*1024 immediate (swizzle invariant to +16k)
    uint32_t bOffS[2];
    {
        int kk = (lane & 7) + ((lane >> 3) & 1) * 8;
        #pragma unroll
        for (int ng = 0; ng < 2; ++ng) {
            int c = ng * 2 + ((lane >> 4) & 1);
            bOffS[ng] = (uint32_t)(kk * 64 + ((c ^ ((kk >> 1) & 3)) << 4));
        }
    }
    // ldsm A (resident): +kb*8192 +k16*4096 immediates (TSWZ invariant mod 8)
    uint32_t aOff0[4];
    {
        int kk = (lane & 7) + ((lane >> 4) & 1) * 8;
        #pragma unroll
        for (int mt = 0; mt < 4; ++mt) {
            int mm = wm * 64 + mt * 16 + ((lane >> 3) & 1) * 8;
            aOff0[mt] = (uint32_t)(A_OFF + kk * 256 + (TSWZ(kk, mm >> 3) << 4));
        }
    }
    uint32_t eOff[4];
    #pragma unroll
    for (int nt = 0; nt < 4; ++nt) {
        int col = wn * 32 + nt * 8 + ((lane & 3) << 1);
        eOff[nt] = (uint32_t)((col >> 4) * 4096 + (((col >> 2) & 3) << 6) + (col & 3));
    }
    const int sgb = mcol + wm * 64 + (lane >> 2);
    const uint32_t colbase = wn * 32;

    // ===== per-warp barrier-free mainloop =====
    const int C = (bx1 - bx0) * 4;     // 4 chunks (32k) per tile

    float acc[4][4][4];
    #pragma unroll
    for (int i = 0; i < 4; ++i)
        #pragma unroll
        for (int j = 0; j < 4; ++j)
            #pragma unroll
            for (int k = 0; k < 4; ++k)
                acc[i][j][k] = 0.0f;

    auto issue = [&](int c) {
        int bx = bx0 + (c >> 2);
        int kb = c & 3;
        const __half* gB = g_B + (size_t)(kb * BK) * NOUT + (uint32_t)bx * 128 + colbase;
        const uint32_t st = ringBase + (c & 3) * STRIP;
        #pragma unroll
        for (int i = 0; i < 4; ++i)
            cp_async16(st + sOffB[i], gB + gOffB[i]);
    };

    auto compute = [&](int c) {
        const uint32_t st = ringBase + (c & 3) * STRIP;
        const uint32_t aB = sbase + (c & 3) * 8192;   // kb == c&3
        #pragma unroll
        for (int k16 = 0; k16 < 2; ++k16) {
            uint32_t br[4][2];
            #pragma unroll
            for (int ng = 0; ng < 2; ++ng) {
                uint32_t b0, b1, b2, b3;
                ldsm4t(b0, b1, b2, b3, st + bOffS[ng] + k16 * 1024);
                br[ng * 2][0] = b0;     br[ng * 2][1] = b1;
                br[ng * 2 + 1][0] = b2; br[ng * 2 + 1][1] = b3;
            }
            #pragma unroll
            for (int mt = 0; mt < 4; ++mt) {
                uint32_t a0, a1, a2, a3;
                ldsm4t(a0, a1, a2, a3, aB + aOff0[mt] + k16 * 4096);
                #pragma unroll
                for (int nt = 0; nt < 4; ++nt)
                    mma16816(acc[mt][nt], a0, a1, a2, a3, br[nt][0], br[nt][1]);
            }
        }
    };

    auto epilogue = [&](int bx) {
        float* obase = out + (size_t)nn * 4194304 + (uint32_t)bx * 32768u;
        #pragma unroll
        for (int mt = 0; mt < 4; ++mt) {
            int sg0 = sgb + mt * 16;
            uint32_t r0 = (uint32_t)((sg0 >> 4) * 256 + (sg0 & 15) * 4);
            int sg1 = sg0 + 8;
            uint32_t r1 = (uint32_t)((sg1 >> 4) * 256 + (sg1 & 15) * 4);
            #pragma unroll
            for (int nt = 0; nt < 4; ++nt) {
                *(float2*)(obase + eOff[nt] + r0) =
                    make_float2(acc[mt][nt][0], acc[mt][nt][1]);
                *(float2*)(obase + eOff[nt] + r1) =
                    make_float2(acc[mt][nt][2], acc[mt][nt][3]);
            }
        }
        #pragma unroll
        for (int i = 0; i < 4; ++i)
            #pragma unroll
            for (int jj = 0; jj < 4; ++jj)
                #pragma unroll
                for (int k = 0; k < 4; ++k)
                    acc[i][jj][k] = 0.0f;
    };

    // prologue: fill 3 of 4 ring slots (per warp)
    #pragma unroll
    for (int c = 0; c < NST - 1; ++c) {
        if (c < C) issue(c);
        cp_commit();
    }

    // steady state: no CTA barriers, per-warp wait_group only
    for (int c = 0; c < C; ++c) {
        cp_wait<NST - 2>();
        int cn = c + NST - 1;
        if (cn < C) issue(cn);
        cp_commit();                 // always commit to keep group numbering
        compute(c);
        if ((c & 3) == 3) epilogue(bx0 + (c >> 2));
    }
}

// ---------------- launch ----------------
extern "C" void kernel_launch(void* const* d_in, const int* in_sizes, int n_in,
                              void* d_out, int out_size) {
    const float* y = (const float*)d_in[0];   // [8][128][256]
    const float* W = (const float*)d_in[1];   // [128][16384]
    float* out = (float*)d_out;

    cudaFuncSetAttribute(fused_kernel,
                         cudaFuncAttributeMaxDynamicSharedMemorySize, SM_TOTAL);
    int nb = 0, sms = 0;
    cudaOccupancyMaxActiveBlocksPerMultiprocessor(&nb, fused_kernel, 256, SM_TOTAL);
    cudaDeviceGetAttribute(&sms, cudaDevAttrMultiProcessorCount, 0);
    int grid = (nb * sms) & ~15;
    if (grid < 16) grid = 16;
    if (grid > 2048) grid = 2048;

    fused_kernel<<<grid, 256, SM_TOTAL>>>(y, W, out);
}

// round 14
// speedup vs baseline: 1.0215x; 1.0215x over previous
#include <cuda_runtime.h>
#include <cuda_fp16.h>
#include <cstdint>

// ---------------- problem constants ----------------
#define B_    8
#define K_    128
#define S_    256
#define NOUT  16384
#define M_    2048
#define BM    128
#define BN    128
#define BK    32
#define NKB   4
#define STAGE_BYTES (BK * 256 * 2)             // A[32][256B] + B[32][256B] = 16KB
#define SM_TOTAL (NKB * STAGE_BYTES)           // 64KB, full-K prefetch

// ---------------- scratch: fp16, SAME layout as sources (no transpose) ----------------
__device__ __align__(16) __half g_A[B_ * K_ * S_];     // [n][k][s]   512 KB
__device__ __align__(16) __half g_B[K_ * NOUT];        // [k][j]      4 MB

// ---------------- helpers ----------------
__device__ __forceinline__ uint32_t smem_u32(const void* p) {
    uint32_t a;
    asm("{ .reg .u64 t; cvta.to.shared.u64 t, %1; cvt.u32.u64 %0, t; }" : "=r"(a) : "l"(p));
    return a;
}
__device__ __forceinline__ void cp_async16(uint32_t saddr, const void* gaddr) {
    asm volatile("cp.async.cg.shared.global [%0], [%1], 16;" :: "r"(saddr), "l"(gaddr));
}
__device__ __forceinline__ void cp_commit() {
    asm volatile("cp.async.commit_group;" ::: "memory");
}
template <int N>
__device__ __forceinline__ void cp_wait() {
    asm volatile("cp.async.wait_group %0;" :: "n"(N) : "memory");
}
__device__ __forceinline__ void ldsm4t(uint32_t& r0, uint32_t& r1, uint32_t& r2, uint32_t& r3,
                                       uint32_t addr) {
    asm volatile("ldmatrix.sync.aligned.m8n8.x4.trans.shared.b16 {%0,%1,%2,%3}, [%4];"
                 : "=r"(r0), "=r"(r1), "=r"(r2), "=r"(r3) : "r"(addr));
}
__device__ __forceinline__ void mma16816(float* d, uint32_t a0, uint32_t a1, uint32_t a2,
                                         uint32_t a3, uint32_t b0, uint32_t b1) {
    asm volatile(
        "mma.sync.aligned.m16n8k16.row.col.f32.f16.f16.f32 "
        "{%0,%1,%2,%3}, {%4,%5,%6,%7}, {%8,%9}, {%0,%1,%2,%3};"
        : "+f"(d[0]), "+f"(d[1]), "+f"(d[2]), "+f"(d[3])
        : "r"(a0), "r"(a1), "r"(a2), "r"(a3), "r"(b0), "r"(b1));
}

// ---------------- pre-kernel: pure streaming fp32 -> fp16 cast ----------------
__global__ __launch_bounds__(256)
void convert_kernel(const float* __restrict__ y, const float* __restrict__ W) {
    const int bid = blockIdx.x;
    const float* s;
    __half* d;
    if (bid < 1024) {
        size_t u = (size_t)bid * 256 + threadIdx.x;     // unit of 8 floats
        s = W + u * 8;  d = g_B + u * 8;
    } else {
        size_t u = (size_t)(bid - 1024) * 256 + threadIdx.x;
        s = y + u * 8;  d = g_A + u * 8;
    }
    float4 v0 = ((const float4*)s)[0];
    float4 v1 = ((const float4*)s)[1];
    __half2 h0 = __floats2half2_rn(v0.x, v0.y);
    __half2 h1 = __floats2half2_rn(v0.z, v0.w);
    __half2 h2 = __floats2half2_rn(v1.x, v1.y);
    __half2 h3 = __floats2half2_rn(v1.z, v1.w);
    uint4 o;
    o.x = *(uint32_t*)&h0; o.y = *(uint32_t*)&h1;
    o.z = *(uint32_t*)&h2; o.w = *(uint32_t*)&h3;
    *(uint4*)d = o;
}

// smem tile layout: [32 k-rows][256B], 16B chunk swizzle  c' = c ^ (k & 7)
#define TSWZ(k, c) ((c) ^ ((k) & 7))

// ---------------- main GEMM kernel: full prefetch, SINGLE rendezvous ----------------
__global__ __launch_bounds__(256, 2)
void gemm_fp16_kernel(float* __restrict__ out) {
    extern __shared__ char smem[];
    const uint32_t sbase = smem_u32(smem);
    const int tid  = threadIdx.x;
    const int lane = tid & 31;
    const int w    = tid >> 5;
    const int wm   = w >> 2;      // 0..1 (64-row strip)
    const int wn   = w & 3;       // 0..3 (32-col strip)
    const int bx   = blockIdx.x;  // n tile 0..127
    const int by   = blockIdx.y;  // m tile 0..15
    const int nn_b = by >> 1;     // batch
    const int mcol = (by & 1) * 128;

    const __half* gA = g_A + (size_t)nn_b * K_ * S_ + mcol;   // rows: +S_ per k
    const __half* gB = g_B + (size_t)bx * BN;                 // rows: +NOUT per k

    float acc[4][4][4];
    #pragma unroll
    for (int i = 0; i < 4; ++i)
        #pragma unroll
        for (int j = 0; j < 4; ++j)
            #pragma unroll
            for (int k = 0; k < 4; ++k)
                acc[i][j][k] = 0.0f;

    // ---- prefetch ALL four K-chunks into 4 independent stages ----
    #pragma unroll
    for (int kb = 0; kb < NKB; ++kb) {
        const int kk0 = kb * BK;
        const uint32_t st = sbase + kb * STAGE_BYTES;
        #pragma unroll
        for (int it = 0; it < 2; ++it) {          // A: 512 chunks
            int ch = tid + it * 256;
            int k  = ch >> 4, c = ch & 15;
            cp_async16(st + k * 256 + (TSWZ(k, c) << 4),
                       gA + (size_t)(kk0 + k) * S_ + c * 8);
        }
        #pragma unroll
        for (int it = 0; it < 2; ++it) {          // B: 512 chunks
            int ch = tid + it * 256;
            int k  = ch >> 4, c = ch & 15;
            cp_async16(st + BK * 256 + k * 256 + (TSWZ(k, c) << 4),
                       gB + (size_t)(kk0 + k) * NOUT + c * 8);
        }
    }
    cp_commit();

    // ---- SINGLE rendezvous: everything resident, then barrier-free compute ----
    cp_wait<0>();
    __syncthreads();

    #pragma unroll
    for (int kb = 0; kb < NKB; ++kb) {
        const uint32_t Ab = sbase + kb * STAGE_BYTES;
        const uint32_t Bb = Ab + BK * 256;
        #pragma unroll
        for (int k16 = 0; k16 < 2; ++k16) {
            uint32_t br[4][2];
            #pragma unroll
            for (int ng = 0; ng < 2; ++ng) {
                int kk = k16 * 16 + (lane & 7) + ((lane >> 3) & 1) * 8;
                int nn = wn * 32 + ng * 16 + ((lane >> 4) & 1) * 8;
                uint32_t addr = Bb + kk * 256 + (TSWZ(kk, nn >> 3) << 4);
                uint32_t b0, b1, b2, b3;
                ldsm4t(b0, b1, b2, b3, addr);
                br[ng * 2][0] = b0;     br[ng * 2][1] = b1;
                br[ng * 2 + 1][0] = b2; br[ng * 2 + 1][1] = b3;
            }
            #pragma unroll
            for (int mt = 0; mt < 4; ++mt) {
                int kk = k16 * 16 + (lane & 7) + ((lane >> 4) & 1) * 8;
                int mm = wm * 64 + mt * 16 + ((lane >> 3) & 1) * 8;
                uint32_t addr = Ab + kk * 256 + (TSWZ(kk, mm >> 3) << 4);
                uint32_t a0, a1, a2, a3;
                ldsm4t(a0, a1, a2, a3, addr);
                #pragma unroll
                for (int nt = 0; nt < 4; ++nt)
                    mma16816(acc[mt][nt], a0, a1, a2, a3, br[nt][0], br[nt][1]);
            }
        }
    }

    // ---- epilogue: direct register -> gmem, coalesced STG.64 ----
    float* obase = out + (size_t)nn_b * 4194304;
    #pragma unroll
    for (int mt = 0; mt < 4; ++mt) {
        #pragma unroll
        for (int nt = 0; nt < 4; ++nt) {
            int col = wn * 32 + nt * 8 + ((lane & 3) << 1);   // local j, even
            int j   = bx * BN + col;
            int p   = j >> 4;
            int q   = (j >> 2) & 3;
            int r   = j & 3;
            int sg0 = mcol + wm * 64 + mt * 16 + (lane >> 2);
            {
                size_t addr = (size_t)p * 4096 + (sg0 >> 4) * 256 + q * 64
                            + (sg0 & 15) * 4 + r;
                *(float2*)(obase + addr) = make_float2(acc[mt][nt][0], acc[mt][nt][1]);
            }
            {
                int sg1 = sg0 + 8;
                size_t addr = (size_t)p * 4096 + (sg1 >> 4) * 256 + q * 64
                            + (sg1 & 15) * 4 + r;
                *(float2*)(obase + addr) = make_float2(acc[mt][nt][2], acc[mt][nt][3]);
            }
        }
    }
}

// ---------------- launch ----------------
extern "C" void kernel_launch(void* const* d_in, const int* in_sizes, int n_in,
                              void* d_out, int out_size) {
    const float* y = (const float*)d_in[0];   // [8][128][256]
    const float* W = (const float*)d_in[1];   // [128][16384]
    float* out = (float*)d_out;

    convert_kernel<<<1152, 256>>>(y, W);

    cudaFuncSetAttribute(gemm_fp16_kernel,
                         cudaFuncAttributeMaxDynamicSharedMemorySize, SM_TOTAL);
    dim3 grid(NOUT / BN, M_ / BM);   // (128, 16)
    gemm_fp16_kernel<<<grid, 256, SM_TOTAL>>>(out);
}

// round 15
// speedup vs baseline: 1.0322x; 1.0105x over previous
#include <cuda_runtime.h>
#include <cuda_fp16.h>
#include <cstdint>

// ---------------- problem constants ----------------
#define B_    8
#define K_    128
#define S_    256
#define NOUT  16384
#define M_    2048
#define BM    128
#define BN    128
#define BK    32
#define NKB   4
#define STAGE_BYTES (BK * 256 * 2)             // A[32][256B] + B[32][256B] = 16KB
#define SM_TOTAL (NKB * STAGE_BYTES)           // 64KB, full-K prefetch

// ---------------- scratch: fp16, SAME layout as sources ----------------
__device__ __align__(16) __half g_A[B_ * K_ * S_];     // [n][k][s]   512 KB
__device__ __align__(16) __half g_B[K_ * NOUT];        // [k][j]      4 MB

// ---------------- helpers ----------------
__device__ __forceinline__ uint32_t smem_u32(const void* p) {
    uint32_t a;
    asm("{ .reg .u64 t; cvta.to.shared.u64 t, %1; cvt.u32.u64 %0, t; }" : "=r"(a) : "l"(p));
    return a;
}
__device__ __forceinline__ void cp_async16(uint32_t saddr, const void* gaddr) {
    asm volatile("cp.async.cg.shared.global [%0], [%1], 16;" :: "r"(saddr), "l"(gaddr));
}
__device__ __forceinline__ void cp_commit() {
    asm volatile("cp.async.commit_group;" ::: "memory");
}
template <int N>
__device__ __forceinline__ void cp_wait() {
    asm volatile("cp.async.wait_group %0;" :: "n"(N) : "memory");
}
__device__ __forceinline__ void ldsm4t(uint32_t& r0, uint32_t& r1, uint32_t& r2, uint32_t& r3,
                                       uint32_t addr) {
    asm volatile("ldmatrix.sync.aligned.m8n8.x4.trans.shared.b16 {%0,%1,%2,%3}, [%4];"
                 : "=r"(r0), "=r"(r1), "=r"(r2), "=r"(r3) : "r"(addr));
}
__device__ __forceinline__ void mma16816(float* d, uint32_t a0, uint32_t a1, uint32_t a2,
                                         uint32_t a3, uint32_t b0, uint32_t b1) {
    asm volatile(
        "mma.sync.aligned.m16n8k16.row.col.f32.f16.f16.f32 "
        "{%0,%1,%2,%3}, {%4,%5,%6,%7}, {%8,%9}, {%0,%1,%2,%3};"
        : "+f"(d[0]), "+f"(d[1]), "+f"(d[2]), "+f"(d[3])
        : "r"(a0), "r"(a1), "r"(a2), "r"(a3), "r"(b0), "r"(b1));
}

// ---------------- pre-kernel: pure streaming fp32 -> fp16 cast ----------------
__global__ __launch_bounds__(256)
void convert_kernel(const float* __restrict__ y, const float* __restrict__ W) {
    const int bid = blockIdx.x;
    const float* s;
    __half* d;
    if (bid < 1024) {
        size_t u = (size_t)bid * 256 + threadIdx.x;
        s = W + u * 8;  d = g_B + u * 8;
    } else {
        size_t u = (size_t)(bid - 1024) * 256 + threadIdx.x;
        s = y + u * 8;  d = g_A + u * 8;
    }
    float4 v0 = ((const float4*)s)[0];
    float4 v1 = ((const float4*)s)[1];
    __half2 h0 = __floats2half2_rn(v0.x, v0.y);
    __half2 h1 = __floats2half2_rn(v0.z, v0.w);
    __half2 h2 = __floats2half2_rn(v1.x, v1.y);
    __half2 h3 = __floats2half2_rn(v1.z, v1.w);
    uint4 o;
    o.x = *(uint32_t*)&h0; o.y = *(uint32_t*)&h1;
    o.z = *(uint32_t*)&h2; o.w = *(uint32_t*)&h3;
    *(uint4*)d = o;
    // PDL: allow the GEMM grid to begin launching while we drain
    cudaTriggerProgrammaticLaunchCompletion();
}

// smem tile layout: [32 k-rows][256B], 16B chunk swizzle  c' = c ^ (k & 7)
#define TSWZ(k, c) ((c) ^ ((k) & 7))

// ---------------- main GEMM kernel (R9 structure + PDL sync) ----------------
__global__ __launch_bounds__(256, 2)
void gemm_fp16_kernel(float* __restrict__ out) {
    extern __shared__ char smem[];
    const uint32_t sbase = smem_u32(smem);
    const int tid  = threadIdx.x;
    const int lane = tid & 31;
    const int w    = tid >> 5;
    const int wm   = w >> 2;      // 0..1 (64-row strip)
    const int wn   = w & 3;       // 0..3 (32-col strip)
    const int bx   = blockIdx.x;  // n tile 0..127
    const int by   = blockIdx.y;  // m tile 0..15
    const int nn_b = by >> 1;     // batch
    const int mcol = (by & 1) * 128;

    const __half* gA = g_A + (size_t)nn_b * K_ * S_ + mcol;
    const __half* gB = g_B + (size_t)bx * BN;

    float acc[4][4][4];
    #pragma unroll
    for (int i = 0; i < 4; ++i)
        #pragma unroll
        for (int j = 0; j < 4; ++j)
            #pragma unroll
            for (int k = 0; k < 4; ++k)
                acc[i][j][k] = 0.0f;

    // PDL: wait until convert's writes are visible before reading scratch
    cudaGridDependencySynchronize();

    // ---- prefetch ALL four K-chunks (stepped groups) ----
    #pragma unroll
    for (int kb = 0; kb < NKB; ++kb) {
        const int kk0 = kb * BK;
        const uint32_t st = sbase + kb * STAGE_BYTES;
        #pragma unroll
        for (int it = 0; it < 2; ++it) {          // A: 512 chunks
            int ch = tid + it * 256;
            int k  = ch >> 4, c = ch & 15;
            cp_async16(st + k * 256 + (TSWZ(k, c) << 4),
                       gA + (size_t)(kk0 + k) * S_ + c * 8);
        }
        #pragma unroll
        for (int it = 0; it < 2; ++it) {          // B: 512 chunks
            int ch = tid + it * 256;
            int k  = ch >> 4, c = ch & 15;
            cp_async16(st + BK * 256 + k * 256 + (TSWZ(k, c) << 4),
                       gB + (size_t)(kk0 + k) * NOUT + c * 8);
        }
        cp_commit();
    }

    auto compute = [&](int kb) {
        const uint32_t Ab = sbase + kb * STAGE_BYTES;
        const uint32_t Bb = Ab + BK * 256;
        #pragma unroll
        for (int k16 = 0; k16 < 2; ++k16) {
            uint32_t br[4][2];
            #pragma unroll
            for (int ng = 0; ng < 2; ++ng) {
                int kk = k16 * 16 + (lane & 7) + ((lane >> 3) & 1) * 8;
                int nn = wn * 32 + ng * 16 + ((lane >> 4) & 1) * 8;
                uint32_t addr = Bb + kk * 256 + (TSWZ(kk, nn >> 3) << 4);
                uint32_t b0, b1, b2, b3;
                ldsm4t(b0, b1, b2, b3, addr);
                br[ng * 2][0] = b0;     br[ng * 2][1] = b1;
                br[ng * 2 + 1][0] = b2; br[ng * 2 + 1][1] = b3;
            }
            #pragma unroll
            for (int mt = 0; mt < 4; ++mt) {
                int kk = k16 * 16 + (lane & 7) + ((lane >> 4) & 1) * 8;
                int mm = wm * 64 + mt * 16 + ((lane >> 3) & 1) * 8;
                uint32_t addr = Ab + kk * 256 + (TSWZ(kk, mm >> 3) << 4);
                uint32_t a0, a1, a2, a3;
                ldsm4t(a0, a1, a2, a3, addr);
                #pragma unroll
                for (int nt = 0; nt < 4; ++nt)
                    mma16816(acc[mt][nt], a0, a1, a2, a3, br[nt][0], br[nt][1]);
            }
        }
    };

    cp_wait<3>(); __syncthreads(); compute(0);
    cp_wait<2>(); __syncthreads(); compute(1);
    cp_wait<1>(); __syncthreads(); compute(2);
    cp_wait<0>(); __syncthreads(); compute(3);

    // ---- epilogue: direct register -> gmem, coalesced STG.64 ----
    float* obase = out + (size_t)nn_b * 4194304;
    #pragma unroll
    for (int mt = 0; mt < 4; ++mt) {
        #pragma unroll
        for (int nt = 0; nt < 4; ++nt) {
            int col = wn * 32 + nt * 8 + ((lane & 3) << 1);
            int j   = bx * BN + col;
            int p   = j >> 4;
            int q   = (j >> 2) & 3;
            int r   = j & 3;
            int sg0 = mcol + wm * 64 + mt * 16 + (lane >> 2);
            {
                size_t addr = (size_t)p * 4096 + (sg0 >> 4) * 256 + q * 64
                            + (sg0 & 15) * 4 + r;
                *(float2*)(obase + addr) = make_float2(acc[mt][nt][0], acc[mt][nt][1]);
            }
            {
                int sg1 = sg0 + 8;
                size_t addr = (size_t)p * 4096 + (sg1 >> 4) * 256 + q * 64
                            + (sg1 & 15) * 4 + r;
                *(float2*)(obase + addr) = make_float2(acc[mt][nt][2], acc[mt][nt][3]);
            }
        }
    }
}

// ---------------- launch ----------------
extern "C" void kernel_launch(void* const* d_in, const int* in_sizes, int n_in,
                              void* d_out, int out_size) {
    const float* y = (const float*)d_in[0];   // [8][128][256]
    const float* W = (const float*)d_in[1];   // [128][16384]
    float* out = (float*)d_out;

    convert_kernel<<<1152, 256>>>(y, W);

    static bool attr_set = false;
    if (!attr_set) {
        cudaFuncSetAttribute(gemm_fp16_kernel,
                             cudaFuncAttributeMaxDynamicSharedMemorySize, SM_TOTAL);
        attr_set = true;
    }

    // GEMM launched with Programmatic Stream Serialization (PDL)
    cudaLaunchConfig_t cfg = {};
    cfg.gridDim  = dim3(NOUT / BN, M_ / BM);   // (128, 16)
    cfg.blockDim = dim3(256, 1, 1);
    cfg.dynamicSmemBytes = SM_TOTAL;
    cfg.stream = 0;
    cudaLaunchAttribute attrs[1];
    attrs[0].id = cudaLaunchAttributeProgrammaticStreamSerialization;
    attrs[0].val.programmaticStreamSerializationAllowed = 1;
    cfg.attrs = attrs;
    cfg.numAttrs = 1;
    cudaLaunchKernelEx(&cfg, gemm_fp16_kernel, out);
}